// round 5
// baseline (speedup 1.0000x reference)
#include <cuda_runtime.h>
#include <cstdint>
#include <cstddef>

typedef unsigned long long u64;

#define TT 512
#define BB 64
#define II 512
#define HH 512
#define G4 2048
#define NB2 128
#define NT2 128

// ---- device-global scratch (allocation-free) ----
__device__ float g_xp[(size_t)TT * G4 * BB];   // [t][gate_row][b]
__device__ float g_hb[2][HH * BB];             // double-buffered h, [hid][b]
__device__ unsigned int g_bar;

// ---- helpers ----
__device__ __forceinline__ u64 dup2f(float x) {
    u64 r; asm("mov.b64 %0, {%1, %1};" : "=l"(r) : "f"(x)); return r;
}
__device__ __forceinline__ void fma2(u64 &d, u64 a, u64 b) {
    asm("fma.rn.f32x2 %0, %1, %2, %0;" : "+l"(d) : "l"(a), "l"(b));
}
__device__ __forceinline__ void cp16(uint32_t s, const void* g) {
    asm volatile("cp.async.cg.shared.global [%0], [%1], 16;" :: "r"(s), "l"(g));
}
__device__ __forceinline__ void cpcommit() { asm volatile("cp.async.commit_group;"); }
template<int N> __device__ __forceinline__ void cpwait() {
    asm volatile("cp.async.wait_group %0;" :: "n"(N));
}
__device__ __forceinline__ float sigm(float x) { return 1.0f / (1.0f + __expf(-x)); }

// ============================================================
// Kernel 1: x_proj[t][g][b] = x @ W_ih^T + b_ih + b_hh
// GEMM M=32768 (t*64+b), N=2048, K=512. 128x128 tile, 8x8 micro, FFMA2.
// ============================================================
__global__ void __launch_bounds__(256, 2) k1_gemm(
    const float* __restrict__ x, const float* __restrict__ Wih,
    const float* __restrict__ bih, const float* __restrict__ bhh)
{
    __shared__ float sm[8704 + 128];
    float* As   = sm;          // [16][136]
    float* Bs   = sm + 2176;   // [16][136]
    float* stage = sm;         // [128 n][68] overlay after compute
    float* bias = sm + 8704;   // [128]

    const int tid = threadIdx.x;
    const int m0 = blockIdx.x * 128;
    const int n0 = blockIdx.y * 128;
    if (blockIdx.x == 0 && blockIdx.y == 0 && tid == 0) g_bar = 0u;  // reset grid barrier each launch

    if (tid < 128) bias[tid] = bih[n0 + tid] + bhh[n0 + tid];

    const int tx = tid & 15;   // n-dir
    const int ty = tid >> 4;   // m-dir

    u64 acc[8][4];
    #pragma unroll
    for (int i = 0; i < 8; i++)
        #pragma unroll
        for (int j = 0; j < 4; j++) acc[i][j] = 0ull;

    const int lr = tid >> 2;   // load row (0..63), +64 for second
    const int cq = tid & 3;    // which float4 of the 16-wide k tile

    for (int kt = 0; kt < 512; kt += 16) {
        __syncthreads();
        #pragma unroll
        for (int h = 0; h < 2; h++) {
            int r = lr + h * 64;
            float4 v = *(const float4*)(x + (size_t)(m0 + r) * II + kt + cq * 4);
            As[(cq*4+0)*136 + r] = v.x; As[(cq*4+1)*136 + r] = v.y;
            As[(cq*4+2)*136 + r] = v.z; As[(cq*4+3)*136 + r] = v.w;
            float4 w = *(const float4*)(Wih + (size_t)(n0 + r) * II + kt + cq * 4);
            Bs[(cq*4+0)*136 + r] = w.x; Bs[(cq*4+1)*136 + r] = w.y;
            Bs[(cq*4+2)*136 + r] = w.z; Bs[(cq*4+3)*136 + r] = w.w;
        }
        __syncthreads();
        #pragma unroll
        for (int k = 0; k < 16; k++) {
            float4 al = *(const float4*)(As + k*136 + ty*8);
            float4 ah = *(const float4*)(As + k*136 + ty*8 + 4);
            float4 bl = *(const float4*)(Bs + k*136 + tx*8);
            float4 bh = *(const float4*)(Bs + k*136 + tx*8 + 4);
            u64 bp0 = ((const u64*)&bl)[0], bp1 = ((const u64*)&bl)[1];
            u64 bp2 = ((const u64*)&bh)[0], bp3 = ((const u64*)&bh)[1];
            float av[8] = {al.x, al.y, al.z, al.w, ah.x, ah.y, ah.z, ah.w};
            #pragma unroll
            for (int i = 0; i < 8; i++) {
                u64 ad = dup2f(av[i]);
                fma2(acc[i][0], ad, bp0); fma2(acc[i][1], ad, bp1);
                fma2(acc[i][2], ad, bp2); fma2(acc[i][3], ad, bp3);
            }
        }
    }

    // Tile covers 2 timesteps (m = t*64 + b, m-tile=128). Stage [n][b], write coalesced.
    const int t0 = m0 >> 6;
    #pragma unroll
    for (int half = 0; half < 2; half++) {
        __syncthreads();
        if ((ty >> 3) == half) {
            int mb = (ty & 7) * 8;  // b within half
            #pragma unroll
            for (int i = 0; i < 8; i++) {
                #pragma unroll
                for (int j = 0; j < 4; j++) {
                    float2 v = *(float2*)&acc[i][j];
                    stage[(tx*8 + 2*j    )*68 + mb + i] = v.x;
                    stage[(tx*8 + 2*j + 1)*68 + mb + i] = v.y;
                }
            }
        }
        __syncthreads();
        float* obase = g_xp + ((size_t)(t0 + half) * G4 + n0) * BB;
        #pragma unroll
        for (int q = 0; q < 8; q++) {
            int e4 = tid + q * 256;      // 0..2047 float4s
            int nn = e4 >> 4;            // 0..127
            int b4 = (e4 & 15) * 4;
            float4 v = *(const float4*)(stage + nn*68 + b4);
            float bs = bias[nn];
            v.x += bs; v.y += bs; v.z += bs; v.w += bs;
            *(float4*)(obase + nn * BB + b4) = v;
        }
    }
}

// ============================================================
// Kernel 2: persistent recurrence. 128 CTAs x 128 thr, single wave.
// CTA owns 4 hidden units (16 gate rows). Weights in smem for all 512 steps.
// h broadcast via cp.async.cg double-buffered 64-k chunks.
// ============================================================
__global__ void __launch_bounds__(NT2, 1) k2_rec(
    const float* __restrict__ Whh, float* __restrict__ out)
{
    extern __shared__ float sm2[];
    float* Ws = sm2;                    // [16][520]
    float* hs = sm2 + 16 * 520;         // [2][64 k][64 b]
    float* gs = hs + 2 * 64 * 64;       // [16][68]
    float* ho = gs + 16 * 68;           // [64 b][4 u]

    const int tid = threadIdx.x;
    const int cta = blockIdx.x;
    const int H0 = cta * 4;

    // Load W_hh rows: local row r = q*4+u  ->  global row q*512 + H0 + u
    for (int i = tid; i < 16 * 128; i += NT2) {
        int r = i >> 7;
        int k4 = i & 127;
        int q = r >> 2, u = r & 3;
        float4 v = *(const float4*)(Whh + (size_t)(q * 512 + H0 + u) * HH + k4 * 4);
        float* d = Ws + r * 520 + k4 * 4;
        d[0] = v.x; d[1] = v.y; d[2] = v.z; d[3] = v.w;
    }
    __syncthreads();

    const int rg = tid >> 4;            // 0..7  (rows rg*2, rg*2+1)
    const int b0 = (tid & 15) * 4;
    const float* W0 = Ws + (rg * 2)     * 520;
    const float* W1 = Ws + (rg * 2 + 1) * 520;

    const uint32_t hs_s = (uint32_t)__cvta_generic_to_shared(hs);

    float c0 = 0.0f, c1 = 0.0f;

    auto prefetch = [&](int kc, const float* hsrc) {
        int bf = kc & 1;
        const float* src = hsrc + kc * 4096;
        uint32_t dst = hs_s + bf * 16384u;
        #pragma unroll
        for (int w = 0; w < 8; w++) {
            int f = tid + w * NT2;
            cp16(dst + (uint32_t)f * 16u, src + f * 4);
        }
        cpcommit();
    };

    for (int t = 0; t < TT; t++) {
        u64 a00 = 0ull, a01 = 0ull, a10 = 0ull, a11 = 0ull;

        if (t > 0) {
            const float* hsrc = g_hb[(t + 1) & 1];   // == (t-1)&1
            prefetch(0, hsrc);
            prefetch(1, hsrc);
            for (int kc = 0; kc < 8; kc++) {
                cpwait<1>();
                __syncthreads();
                const float* hb  = hs + (kc & 1) * 4096;
                const float* w0p = W0 + kc * 64;
                const float* w1p = W1 + kc * 64;
                #pragma unroll
                for (int kk = 0; kk < 64; kk += 4) {
                    float4 w0v = *(const float4*)(w0p + kk);
                    float4 w1v = *(const float4*)(w1p + kk);
                    float w0a[4] = {w0v.x, w0v.y, w0v.z, w0v.w};
                    float w1a[4] = {w1v.x, w1v.y, w1v.z, w1v.w};
                    #pragma unroll
                    for (int j = 0; j < 4; j++) {
                        float4 hv = *(const float4*)(hb + (kk + j) * 64 + b0);
                        u64 h0 = ((const u64*)&hv)[0];
                        u64 h1 = ((const u64*)&hv)[1];
                        u64 d0 = dup2f(w0a[j]);
                        u64 d1 = dup2f(w1a[j]);
                        fma2(a00, d0, h0); fma2(a01, d0, h1);
                        fma2(a10, d1, h0); fma2(a11, d1, h1);
                    }
                }
                __syncthreads();
                if (kc < 6) prefetch(kc + 2, hsrc);
            }
        }

        // dump partial dots to gs[16][68]
        {
            float2 v;
            int ra = (rg * 2) * 68, rb = (rg * 2 + 1) * 68;
            v = *(float2*)&a00; gs[ra + b0 + 0] = v.x; gs[ra + b0 + 1] = v.y;
            v = *(float2*)&a01; gs[ra + b0 + 2] = v.x; gs[ra + b0 + 3] = v.y;
            v = *(float2*)&a10; gs[rb + b0 + 0] = v.x; gs[rb + b0 + 1] = v.y;
            v = *(float2*)&a11; gs[rb + b0 + 2] = v.x; gs[rb + b0 + 3] = v.y;
        }
        __syncthreads();

        // gate math: thread handles (u,b) pairs p = tid and tid+128
        const float* xpb = g_xp + (size_t)t * G4 * BB;
        #pragma unroll
        for (int pp = 0; pp < 2; pp++) {
            int p = tid + pp * NT2;
            int u = p >> 6, b = p & 63;
            float gi = gs[(0  + u) * 68 + b] + xpb[(size_t)(0    + H0 + u) * BB + b];
            float gf = gs[(4  + u) * 68 + b] + xpb[(size_t)(512  + H0 + u) * BB + b];
            float gg = gs[(8  + u) * 68 + b] + xpb[(size_t)(1024 + H0 + u) * BB + b];
            float go = gs[(12 + u) * 68 + b] + xpb[(size_t)(1536 + H0 + u) * BB + b];
            float si = sigm(gi), sf = sigm(gf), so = sigm(go);
            float tg = tanhf(gg);
            float c = (pp ? c1 : c0);
            c = sf * c + si * tg;
            if (pp) c1 = c; else c0 = c;
            float h = so * tanhf(c);
            g_hb[t & 1][(H0 + u) * BB + b] = h;   // coalesced, [hid][b]
            ho[b * 4 + u] = h;
        }
        __syncthreads();

        // coalesced-ish d_out[t][b][hid] write via float4 staging
        if (tid < 64) {
            float4 v = *(const float4*)(ho + tid * 4);
            *(float4*)(out + ((size_t)t * BB + tid) * HH + H0) = v;
        }

        // grid barrier (monotonic counter; g_bar reset by k1 each launch)
        __syncthreads();
        if (tid == 0) {
            __threadfence();
            atomicAdd(&g_bar, 1u);
            unsigned tgt = (unsigned)(t + 1) * NB2;
            unsigned v;
            do {
                asm volatile("ld.global.acquire.gpu.u32 %0, [%1];" : "=r"(v) : "l"(&g_bar));
            } while (v < tgt);
        }
        __syncthreads();
    }
}

// ============================================================
extern "C" void kernel_launch(void* const* d_in, const int* in_sizes, int n_in,
                              void* d_out, int out_size)
{
    const float* x   = (const float*)d_in[0];
    const float* Wih = (const float*)d_in[1];
    const float* Whh = (const float*)d_in[2];
    const float* bih = (const float*)d_in[3];
    const float* bhh = (const float*)d_in[4];
    float* out = (float*)d_out;

    dim3 g1(256, 16);
    k1_gemm<<<g1, 256>>>(x, Wih, bih, bhh);

    const int smem2 = (16 * 520 + 2 * 64 * 64 + 16 * 68 + 64 * 4) * 4;
    cudaFuncSetAttribute(k2_rec, cudaFuncAttributeMaxDynamicSharedMemorySize, smem2);
    k2_rec<<<NB2, NT2, smem2>>>(Whh, out);
}